// round 3
// baseline (speedup 1.0000x reference)
#include <cuda_runtime.h>
#include <math.h>

#define GG 128
#define NN 512
#define NV (GG*NN)          // 65536 nodes
#define HH 128              // hidden/feature dim
#define EE 2097152          // directed edges (2 * G * E_HALF)
#define EPG 16384           // edges per graph
#define LL 5
#define CC 10

// Scratch (device globals: allocation-free per harness rules)
__device__ float g_bufA[NV * HH];          // 32 MB
__device__ float g_bufB[NV * HH];          // 32 MB
__device__ int   g_row_ptr[NV + 1];
__device__ int   g_cursor[NV];
__device__ int   g_edge_src[EE];           // 8 MB

// ---------------------------------------------------------------- CSR build
__global__ void k_zero() {
    int i = blockIdx.x * blockDim.x + threadIdx.x;
    if (i < NV) g_cursor[i] = 0;
}

__global__ void k_hist(const int* __restrict__ dst) {
    int i = blockIdx.x * blockDim.x + threadIdx.x;
    int stride = gridDim.x * blockDim.x;
    for (int e = i; e < EE; e += stride)
        atomicAdd(&g_cursor[dst[e]], 1);
}

// Per-graph exclusive scan of in-degrees. Graph g's edge slots span
// [g*EPG, (g+1)*EPG) and all its dst indices live in [g*NN, (g+1)*NN),
// so each CTA scans 512 counts independently.
__global__ void k_scan() {
    __shared__ int s[NN];
    int g = blockIdx.x, t = threadIdx.x;
    int v = g * NN + t;
    int c = g_cursor[v];
    s[t] = c;
    __syncthreads();
    for (int off = 1; off < NN; off <<= 1) {
        int val = (t >= off) ? s[t - off] : 0;
        __syncthreads();
        s[t] += val;
        __syncthreads();
    }
    int start = g * EPG + s[t] - c;   // exclusive prefix
    g_row_ptr[v] = start;
    g_cursor[v]  = start;             // scatter cursor
    if (v == 0) g_row_ptr[NV] = EE;
}

__global__ void k_scatter(const int* __restrict__ src, const int* __restrict__ dst) {
    int i = blockIdx.x * blockDim.x + threadIdx.x;
    int stride = gridDim.x * blockDim.x;
    for (int e = i; e < EE; e += stride) {
        int pos = atomicAdd(&g_cursor[dst[e]], 1);
        g_edge_src[pos] = src[e];
    }
}

// ---------------------------------------------------------------- SpMM + combine
// One warp per node: lane owns one float4 (4 of 128 feats).
// U[v] = (1+eps_l)*h[v] + sum_{e: dst=v} h[src[e]]
__global__ void __launch_bounds__(256) k_spmm(const float* __restrict__ xin,
                                              const float* __restrict__ eps,
                                              int layer, int ssel, int dsel) {
    const float* hin = (ssel == 0) ? xin : (ssel == 1 ? g_bufA : g_bufB);
    float*       uout = (dsel == 1) ? g_bufA : g_bufB;

    int wid  = (blockIdx.x * blockDim.x + threadIdx.x) >> 5;
    int lane = threadIdx.x & 31;
    if (wid >= NV) return;

    float e1 = 1.0f + __ldg(&eps[layer]);
    const float4* hin4 = (const float4*)hin;
    int base = wid * (HH / 4) + lane;

    float4 h0 = hin4[base];
    float4 acc;
    acc.x = e1 * h0.x; acc.y = e1 * h0.y; acc.z = e1 * h0.z; acc.w = e1 * h0.w;

    int e    = g_row_ptr[wid];
    int eend = g_row_ptr[wid + 1];

    for (; e + 4 <= eend; e += 4) {
        int s0 = g_edge_src[e + 0];
        int s1 = g_edge_src[e + 1];
        int s2 = g_edge_src[e + 2];
        int s3 = g_edge_src[e + 3];
        float4 f0 = hin4[s0 * (HH / 4) + lane];
        float4 f1 = hin4[s1 * (HH / 4) + lane];
        float4 f2 = hin4[s2 * (HH / 4) + lane];
        float4 f3 = hin4[s3 * (HH / 4) + lane];
        acc.x += f0.x; acc.y += f0.y; acc.z += f0.z; acc.w += f0.w;
        acc.x += f1.x; acc.y += f1.y; acc.z += f1.z; acc.w += f1.w;
        acc.x += f2.x; acc.y += f2.y; acc.z += f2.z; acc.w += f2.w;
        acc.x += f3.x; acc.y += f3.y; acc.z += f3.z; acc.w += f3.w;
    }
    for (; e < eend; e++) {
        int s0 = g_edge_src[e];
        float4 f0 = hin4[s0 * (HH / 4) + lane];
        acc.x += f0.x; acc.y += f0.y; acc.z += f0.z; acc.w += f0.w;
    }
    ((float4*)uout)[base] = acc;
}

// ---------------------------------------------------------------- GEMM + bias + relu (in place)
// h[v,:] = relu(U[v,:] @ W_l + b_l). Row-local -> safe in place.
// 256 thr: warp ty owns rows [blk*64 + ty*8, +8), lane tx owns cols [tx*4, +4).
__global__ void __launch_bounds__(256) k_gemm(const float* __restrict__ W,
                                              const float* __restrict__ b,
                                              int layer, int bufsel) {
    float* u = (bufsel == 1) ? g_bufA : g_bufB;
    const float* Wl = W + layer * HH * HH;
    const float* bl = b + layer * HH;

    int tx = threadIdx.x & 31, ty = threadIdx.x >> 5;
    int row0 = blockIdx.x * 64 + ty * 8;
    int c0 = tx * 4;

    float acc[8][4];
    float4 bb = __ldg((const float4*)(bl + c0));
#pragma unroll
    for (int i = 0; i < 8; i++) {
        acc[i][0] = bb.x; acc[i][1] = bb.y; acc[i][2] = bb.z; acc[i][3] = bb.w;
    }

    for (int kk = 0; kk < HH; kk += 4) {
        float4 w0 = __ldg((const float4*)(Wl + (kk + 0) * HH + c0));
        float4 w1 = __ldg((const float4*)(Wl + (kk + 1) * HH + c0));
        float4 w2 = __ldg((const float4*)(Wl + (kk + 2) * HH + c0));
        float4 w3 = __ldg((const float4*)(Wl + (kk + 3) * HH + c0));
        float4 uu[8];
#pragma unroll
        for (int i = 0; i < 8; i++)
            uu[i] = *(const float4*)(u + (row0 + i) * HH + kk);
#pragma unroll
        for (int i = 0; i < 8; i++) {
            acc[i][0] += uu[i].x * w0.x + uu[i].y * w1.x + uu[i].z * w2.x + uu[i].w * w3.x;
            acc[i][1] += uu[i].x * w0.y + uu[i].y * w1.y + uu[i].z * w2.y + uu[i].w * w3.y;
            acc[i][2] += uu[i].x * w0.z + uu[i].y * w1.z + uu[i].z * w2.z + uu[i].w * w3.z;
            acc[i][3] += uu[i].x * w0.w + uu[i].y * w1.w + uu[i].z * w2.w + uu[i].w * w3.w;
        }
    }
#pragma unroll
    for (int i = 0; i < 8; i++) {
        float4 o;
        o.x = fmaxf(acc[i][0], 0.f);
        o.y = fmaxf(acc[i][1], 0.f);
        o.z = fmaxf(acc[i][2], 0.f);
        o.w = fmaxf(acc[i][3], 0.f);
        *((float4*)(u + (row0 + i) * HH + c0)) = o;
    }
}

// ---------------------------------------------------------------- readout + FCs + softmax
__global__ void __launch_bounds__(256) k_readout(const float* __restrict__ fc1w,
                                                 const float* __restrict__ fc1b,
                                                 const float* __restrict__ fc2w,
                                                 const float* __restrict__ fc2b,
                                                 float* __restrict__ out,
                                                 int bufsel) {
    const float* h = (bufsel == 1) ? g_bufA : g_bufB;
    __shared__ float tmp[256];
    __shared__ float hg[HH];
    __shared__ float a1[HH];
    __shared__ float z[CC];
    __shared__ float ez[CC];

    int g = blockIdx.x;
    int t = threadIdx.x;
    int f = t & 127, half = t >> 7;

    const float* base = h + (size_t)g * NN * HH + half * 256 * HH + f;
    float s = 0.f;
#pragma unroll 8
    for (int r = 0; r < 256; r++) s += base[r * HH];
    tmp[t] = s;
    __syncthreads();
    if (half == 0) hg[f] = tmp[f] + tmp[f + 128];
    __syncthreads();

    if (t < HH) {
        float acc = fc1b[t];
        for (int k = 0; k < HH; k++) acc += hg[k] * __ldg(&fc1w[k * HH + t]);
        a1[t] = fmaxf(acc, 0.f);
    }
    __syncthreads();

    if (t < CC) {
        float acc = fc2b[t];
        for (int k = 0; k < HH; k++) acc += a1[k] * __ldg(&fc2w[k * CC + t]);
        z[t] = acc;
    }
    __syncthreads();

    if (t < CC) {
        float m = z[0];
#pragma unroll
        for (int j = 1; j < CC; j++) m = fmaxf(m, z[j]);
        ez[t] = expf(z[t] - m);
    }
    __syncthreads();

    if (t < CC) {
        float ssum = 0.f;
#pragma unroll
        for (int j = 0; j < CC; j++) ssum += ez[j];
        out[g * CC + t] = ez[t] / ssum;
    }
}

// ---------------------------------------------------------------- launch
extern "C" void kernel_launch(void* const* d_in, const int* in_sizes, int n_in,
                              void* d_out, int out_size) {
    const float* x    = (const float*)d_in[0];
    const float* eps  = (const float*)d_in[1];
    const float* W    = (const float*)d_in[2];
    const float* b    = (const float*)d_in[3];
    const float* fc1w = (const float*)d_in[4];
    const float* fc1b = (const float*)d_in[5];
    const float* fc2w = (const float*)d_in[6];
    const float* fc2b = (const float*)d_in[7];
    const int*   src  = (const int*)d_in[8];
    const int*   dst  = (const int*)d_in[9];
    float* out = (float*)d_out;

    // CSR build (per launch; cheap vs. the 5 layers)
    k_zero<<<NV / 256, 256>>>();
    k_hist<<<2048, 256>>>(dst);
    k_scan<<<GG, NN>>>();
    k_scatter<<<2048, 256>>>(src, dst);

    // Layers. ssel: 0=x, 1=bufA, 2=bufB. dsel/bufsel: 1=bufA, 2=bufB.
    // 0: x->A, 1: A->B, 2: B->A, 3: A->B, 4: B->A. Final h in A.
    const int ssel[LL] = {0, 1, 2, 1, 2};
    const int dsel[LL] = {1, 2, 1, 2, 1};
    for (int l = 0; l < LL; l++) {
        k_spmm<<<NV / 8, 256>>>(x, eps, l, ssel[l], dsel[l]);
        k_gemm<<<NV / 64, 256>>>(W, b, l, dsel[l]);
    }

    k_readout<<<GG, 256>>>(fc1w, fc1b, fc2w, fc2b, out, 1);
}

// round 4
// speedup vs baseline: 1.8321x; 1.8321x over previous
#include <cuda_runtime.h>
#include <cuda_bf16.h>
#include <math.h>

#define GG 128
#define NN 512
#define NV (GG*NN)          // 65536 nodes
#define HH 128              // hidden/feature dim
#define EE 2097152          // directed edges (2 * G * E_HALF)
#define EHALF 8192
#define EPG 16384           // directed edges per graph
#define LL 5
#define CC 10

// Scratch (device globals: allocation-free per harness rules)
__device__ float    g_bufA[NV * HH];        // 32 MB
__device__ float    g_bufB[NV * HH];        // 32 MB
__device__ int      g_row_ptr[NV + 1];
__device__ int      g_edge_src[EE];         // 8 MB
__device__ unsigned g_Wth[LL * HH * 64];    // W^T hi, packed bf16 k-pairs [l][n][kw]
__device__ unsigned g_Wtl[LL * HH * 64];    // W^T lo

// ---------------------------------------------------------------- fused CSR build
// One CTA per graph: counting sort of that graph's 16384 directed edges by dst.
// Graph g's edges live at [g*EHALF, (g+1)*EHALF) and [GG*EHALF + g*EHALF, ...).
// All its dst indices are in [g*NN, (g+1)*NN) so (dst & (NN-1)) is the local id.
__global__ void __launch_bounds__(512) k_csr(const int* __restrict__ src,
                                             const int* __restrict__ dst) {
    __shared__ int cnt[NN];
    __shared__ int pos[NN];
    int g = blockIdx.x, t = threadIdx.x;
    cnt[t] = 0;
    __syncthreads();

    int base1 = g * EHALF;
    int base2 = GG * EHALF + g * EHALF;
    for (int i = t; i < EHALF; i += 512) {
        atomicAdd(&cnt[dst[base1 + i] & (NN - 1)], 1);
        atomicAdd(&cnt[dst[base2 + i] & (NN - 1)], 1);
    }
    __syncthreads();

    int c = cnt[t];
    pos[t] = c;
    __syncthreads();
    for (int off = 1; off < NN; off <<= 1) {
        int v = (t >= off) ? pos[t - off] : 0;
        __syncthreads();
        pos[t] += v;
        __syncthreads();
    }
    int startLocal = pos[t] - c;               // exclusive prefix within graph
    g_row_ptr[g * NN + t] = g * EPG + startLocal;
    cnt[t] = startLocal;                       // local scatter cursor
    if (g == 0 && t == 0) g_row_ptr[NV] = EE;
    __syncthreads();

    int* eout = g_edge_src + g * EPG;
    for (int i = t; i < EHALF; i += 512) {
        int d = dst[base1 + i] & (NN - 1);
        int p = atomicAdd(&cnt[d], 1);
        eout[p] = src[base1 + i];
        d = dst[base2 + i] & (NN - 1);
        p = atomicAdd(&cnt[d], 1);
        eout[p] = src[base2 + i];
    }
}

// ---------------------------------------------------------------- W prep: transpose + bf16 hi/lo split
// g_Wth[l][n][kw] = bf16x2{ W[l][2kw][n], W[l][2kw+1][n] }  (hi part); g_Wtl = residual.
__global__ void k_prepw(const float* __restrict__ W) {
    int i = blockIdx.x * blockDim.x + threadIdx.x;
    if (i >= LL * HH * 64) return;
    int kw = i & 63;
    int n  = (i >> 6) & (HH - 1);
    int l  = i >> 13;
    const float* Wl = W + l * HH * HH;
    float w0 = Wl[(2 * kw) * HH + n];
    float w1 = Wl[(2 * kw + 1) * HH + n];
    __nv_bfloat162 h = __float22bfloat162_rn(make_float2(w0, w1));
    float2 hf = __bfloat1622float2(h);
    __nv_bfloat162 lo = __float22bfloat162_rn(make_float2(w0 - hf.x, w1 - hf.y));
    g_Wth[i] = *reinterpret_cast<unsigned*>(&h);
    g_Wtl[i] = *reinterpret_cast<unsigned*>(&lo);
}

// ---------------------------------------------------------------- SpMM + combine
// One warp per node: lane owns one float4 (4 of 128 feats).
__global__ void __launch_bounds__(256) k_spmm(const float* __restrict__ xin,
                                              const float* __restrict__ eps,
                                              int layer, int ssel, int dsel) {
    const float* hin  = (ssel == 0) ? xin : (ssel == 1 ? g_bufA : g_bufB);
    float*       uout = (dsel == 1) ? g_bufA : g_bufB;

    int wid  = (blockIdx.x * blockDim.x + threadIdx.x) >> 5;
    int lane = threadIdx.x & 31;
    if (wid >= NV) return;

    float e1 = 1.0f + __ldg(&eps[layer]);
    const float4* hin4 = (const float4*)hin;
    int base = wid * (HH / 4) + lane;

    float4 h0 = hin4[base];
    float4 acc;
    acc.x = e1 * h0.x; acc.y = e1 * h0.y; acc.z = e1 * h0.z; acc.w = e1 * h0.w;

    int e    = g_row_ptr[wid];
    int eend = g_row_ptr[wid + 1];

    for (; e + 4 <= eend; e += 4) {
        int s0 = g_edge_src[e + 0];
        int s1 = g_edge_src[e + 1];
        int s2 = g_edge_src[e + 2];
        int s3 = g_edge_src[e + 3];
        float4 f0 = hin4[s0 * (HH / 4) + lane];
        float4 f1 = hin4[s1 * (HH / 4) + lane];
        float4 f2 = hin4[s2 * (HH / 4) + lane];
        float4 f3 = hin4[s3 * (HH / 4) + lane];
        acc.x += f0.x; acc.y += f0.y; acc.z += f0.z; acc.w += f0.w;
        acc.x += f1.x; acc.y += f1.y; acc.z += f1.z; acc.w += f1.w;
        acc.x += f2.x; acc.y += f2.y; acc.z += f2.z; acc.w += f2.w;
        acc.x += f3.x; acc.y += f3.y; acc.z += f3.z; acc.w += f3.w;
    }
    for (; e < eend; e++) {
        int s0 = g_edge_src[e];
        float4 f0 = hin4[s0 * (HH / 4) + lane];
        acc.x += f0.x; acc.y += f0.y; acc.z += f0.z; acc.w += f0.w;
    }
    ((float4*)uout)[base] = acc;
}

// ---------------------------------------------------------------- tensor-core GEMM + bias + relu
// h[v,:] = relu(U[v,:] @ W_l + b_l), in place. 2xbf16 split (hi/lo), fp32 accum.
// CTA: 256 thr = 8 warps; tile 64 rows x 128 cols; warp = 16 rows x 64 cols.
// mma.sync.m16n8k16.row.col.f32.bf16.bf16.f32 — 3 passes: Uh*Wh + Ul*Wh + Uh*Wl.

#define SU_STRIDE 132                          // fp32 words per U row (pad 4)
#define SW_STRIDE 68                           // uint32 words per W^T row (pad 4)
#define SMEM_GEMM (64*SU_STRIDE*4 + 2*HH*SW_STRIDE*4 + HH*4)

__device__ __forceinline__ void split2(float2 f, unsigned& hi, unsigned& lo) {
    __nv_bfloat162 h = __float22bfloat162_rn(f);
    float2 hf = __bfloat1622float2(h);
    __nv_bfloat162 l = __float22bfloat162_rn(make_float2(f.x - hf.x, f.y - hf.y));
    hi = *reinterpret_cast<unsigned*>(&h);
    lo = *reinterpret_cast<unsigned*>(&l);
}

#define MMA_BF16(C, A, B0, B1)                                                  \
    asm volatile("mma.sync.aligned.m16n8k16.row.col.f32.bf16.bf16.f32 "          \
                 "{%0,%1,%2,%3}, {%4,%5,%6,%7}, {%8,%9}, {%0,%1,%2,%3};"         \
                 : "+f"(C[0]), "+f"(C[1]), "+f"(C[2]), "+f"(C[3])                \
                 : "r"(A[0]), "r"(A[1]), "r"(A[2]), "r"(A[3]), "r"(B0), "r"(B1))

__global__ void __launch_bounds__(256) k_gemm_tc(const float* __restrict__ b,
                                                 int layer, int bufsel) {
    float* u = (bufsel == 1) ? g_bufA : g_bufB;

    extern __shared__ char smem[];
    float*    sU  = (float*)smem;                                   // [64][132]
    unsigned* sWh = (unsigned*)(smem + 64 * SU_STRIDE * 4);         // [128][68]
    unsigned* sWl = sWh + HH * SW_STRIDE;                           // [128][68]
    float*    sB  = (float*)(sWl + HH * SW_STRIDE);                 // [128]

    int tid = threadIdx.x;
    int rowBase = blockIdx.x * 64;

    // ---- stage U (64x128 fp32) ----
    {
        const float4* u4 = (const float4*)(u + (size_t)rowBase * HH);
#pragma unroll
        for (int k = 0; k < 8; k++) {
            int q = tid + k * 256;              // 2048 float4
            int r = q >> 5, c4 = q & 31;
            float4 v = u4[r * 32 + c4];
            *(float4*)(sU + r * SU_STRIDE + c4 * 4) = v;
        }
    }
    // ---- stage W^T hi/lo (128x64 words each) ----
    {
        const uint4* wh4 = (const uint4*)(g_Wth + layer * HH * 64);
        const uint4* wl4 = (const uint4*)(g_Wtl + layer * HH * 64);
#pragma unroll
        for (int k = 0; k < 8; k++) {
            int q = tid + k * 256;              // 2048 uint4
            int n = q >> 4, c = (q & 15) * 4;
            *(uint4*)(sWh + n * SW_STRIDE + c) = wh4[q];
            *(uint4*)(sWl + n * SW_STRIDE + c) = wl4[q];
        }
    }
    if (tid < HH) sB[tid] = b[layer * HH + tid];
    __syncthreads();

    int warp = tid >> 5, lane = tid & 31;
    int wm = warp & 3, wn = warp >> 2;
    int r0 = wm * 16, n0 = wn * 64;
    int g  = lane >> 2, tg = lane & 3;

    float acc[8][4];
#pragma unroll
    for (int j = 0; j < 8; j++) {
        acc[j][0] = 0.f; acc[j][1] = 0.f; acc[j][2] = 0.f; acc[j][3] = 0.f;
    }

    const float* uA = sU + (r0 + g) * SU_STRIDE + 2 * tg;
    const float* uB = sU + (r0 + g + 8) * SU_STRIDE + 2 * tg;

#pragma unroll
    for (int ks = 0; ks < 8; ks++) {
        int k0 = ks * 16;
        unsigned ah[4], al[4];
        split2(*(const float2*)(uA + k0),     ah[0], al[0]);
        split2(*(const float2*)(uB + k0),     ah[1], al[1]);
        split2(*(const float2*)(uA + k0 + 8), ah[2], al[2]);
        split2(*(const float2*)(uB + k0 + 8), ah[3], al[3]);

        int kp = ks * 8 + tg;
#pragma unroll
        for (int j = 0; j < 8; j++) {
            const unsigned* wh = sWh + (n0 + j * 8 + g) * SW_STRIDE + kp;
            const unsigned* wl = sWl + (n0 + j * 8 + g) * SW_STRIDE + kp;
            unsigned bh0 = wh[0], bh1 = wh[4];
            unsigned bl0 = wl[0], bl1 = wl[4];
            MMA_BF16(acc[j], ah, bh0, bh1);
            MMA_BF16(acc[j], al, bh0, bh1);
            MMA_BF16(acc[j], ah, bl0, bl1);
        }
    }

    // ---- epilogue: bias + relu, store fp32 in place ----
    int rA = rowBase + r0 + g;
    int rB = rA + 8;
#pragma unroll
    for (int j = 0; j < 8; j++) {
        int c = n0 + j * 8 + 2 * tg;
        float b0 = sB[c], b1 = sB[c + 1];
        float2 oA, oB;
        oA.x = fmaxf(acc[j][0] + b0, 0.f);
        oA.y = fmaxf(acc[j][1] + b1, 0.f);
        oB.x = fmaxf(acc[j][2] + b0, 0.f);
        oB.y = fmaxf(acc[j][3] + b1, 0.f);
        *(float2*)(u + rA * HH + c) = oA;
        *(float2*)(u + rB * HH + c) = oB;
    }
}

// ---------------------------------------------------------------- readout + FCs + softmax
__global__ void __launch_bounds__(256) k_readout(const float* __restrict__ fc1w,
                                                 const float* __restrict__ fc1b,
                                                 const float* __restrict__ fc2w,
                                                 const float* __restrict__ fc2b,
                                                 float* __restrict__ out,
                                                 int bufsel) {
    const float* h = (bufsel == 1) ? g_bufA : g_bufB;
    __shared__ float tmp[256];
    __shared__ float hg[HH];
    __shared__ float a1[HH];
    __shared__ float z[CC];
    __shared__ float ez[CC];

    int g = blockIdx.x;
    int t = threadIdx.x;
    int f = t & 127, half = t >> 7;

    const float* base = h + (size_t)g * NN * HH + half * 256 * HH + f;
    float s = 0.f;
#pragma unroll 8
    for (int r = 0; r < 256; r++) s += base[r * HH];
    tmp[t] = s;
    __syncthreads();
    if (half == 0) hg[f] = tmp[f] + tmp[f + 128];
    __syncthreads();

    if (t < HH) {
        float acc = fc1b[t];
        for (int k = 0; k < HH; k++) acc += hg[k] * __ldg(&fc1w[k * HH + t]);
        a1[t] = fmaxf(acc, 0.f);
    }
    __syncthreads();

    if (t < CC) {
        float acc = fc2b[t];
        for (int k = 0; k < HH; k++) acc += a1[k] * __ldg(&fc2w[k * CC + t]);
        z[t] = acc;
    }
    __syncthreads();

    if (t < CC) {
        float m = z[0];
#pragma unroll
        for (int j = 1; j < CC; j++) m = fmaxf(m, z[j]);
        ez[t] = expf(z[t] - m);
    }
    __syncthreads();

    if (t < CC) {
        float ssum = 0.f;
#pragma unroll
        for (int j = 0; j < CC; j++) ssum += ez[j];
        out[g * CC + t] = ez[t] / ssum;
    }
}

// ---------------------------------------------------------------- launch
extern "C" void kernel_launch(void* const* d_in, const int* in_sizes, int n_in,
                              void* d_out, int out_size) {
    const float* x    = (const float*)d_in[0];
    const float* eps  = (const float*)d_in[1];
    const float* W    = (const float*)d_in[2];
    const float* b    = (const float*)d_in[3];
    const float* fc1w = (const float*)d_in[4];
    const float* fc1b = (const float*)d_in[5];
    const float* fc2w = (const float*)d_in[6];
    const float* fc2b = (const float*)d_in[7];
    const int*   src  = (const int*)d_in[8];
    const int*   dst  = (const int*)d_in[9];
    float* out = (float*)d_out;

    cudaFuncSetAttribute(k_gemm_tc, cudaFuncAttributeMaxDynamicSharedMemorySize,
                         SMEM_GEMM);

    k_csr<<<GG, 512>>>(src, dst);
    k_prepw<<<(LL * HH * 64 + 255) / 256, 256>>>(W);

    // 0: x->A, 1: A->B, 2: B->A, 3: A->B, 4: B->A. Final h in A.
    const int ssel[LL] = {0, 1, 2, 1, 2};
    const int dsel[LL] = {1, 2, 1, 2, 1};
    for (int l = 0; l < LL; l++) {
        k_spmm<<<NV / 8, 256>>>(x, eps, l, ssel[l], dsel[l]);
        k_gemm_tc<<<NV / 64, 256, SMEM_GEMM>>>(b, l, dsel[l]);
    }

    k_readout<<<GG, 256>>>(fc1w, fc1b, fc2w, fc2b, out, 1);
}